// round 1
// baseline (speedup 1.0000x reference)
#include <cuda_runtime.h>
#include <cuda_bf16.h>
#include <cstdint>

#define BB 4
#define SS 4096
#define DD 128

// scratch for normalized q (scaled by 1/temp, tf32-rounded) and normalized k
__device__ float g_qn[(size_t)BB * SS * DD];
__device__ float g_kn[(size_t)BB * SS * DD];

__device__ __forceinline__ float to_tf32(float x) {
    asm("cvt.rna.tf32.f32 %0, %0;" : "+f"(x));
    return x;
}

__device__ __forceinline__ void mma8(float c[4], const uint32_t a[4], const uint32_t b[2]) {
    asm volatile(
        "mma.sync.aligned.m16n8k8.row.col.f32.tf32.tf32.f32 "
        "{%0,%1,%2,%3}, {%4,%5,%6,%7}, {%8,%9}, {%0,%1,%2,%3};"
        : "+f"(c[0]), "+f"(c[1]), "+f"(c[2]), "+f"(c[3])
        : "r"(a[0]), "r"(a[1]), "r"(a[2]), "r"(a[3]), "r"(b[0]), "r"(b[1]));
}

// ---------------------------------------------------------------------------
// Kernel 1: L2-normalize q (scaled by 1/temp) and k; tf32-round both.
// One warp per row, 32768 rows total.
// ---------------------------------------------------------------------------
__global__ __launch_bounds__(256)
void norm_kernel(const float* __restrict__ q, const float* __restrict__ k,
                 const float* __restrict__ temp) {
    int warp = (blockIdx.x * blockDim.x + threadIdx.x) >> 5;
    int lane = threadIdx.x & 31;
    if (warp >= 2 * BB * SS) return;
    bool is_q = warp < BB * SS;
    size_t row = is_q ? (size_t)warp : (size_t)(warp - BB * SS);
    const float4* src = (const float4*)((is_q ? q : k) + row * DD);
    float4* dst = (float4*)((is_q ? g_qn : g_kn) + row * DD);

    float4 v = src[lane];
    float ss = v.x * v.x + v.y * v.y + v.z * v.z + v.w * v.w;
    #pragma unroll
    for (int o = 16; o > 0; o >>= 1) ss += __shfl_xor_sync(0xffffffffu, ss, o);
    float n = sqrtf(ss);
    float inv = 1.0f / fmaxf(n, 1e-12f);
    if (is_q) inv *= (1.0f / temp[0]);   // fold 1/temp into qn
    v.x = to_tf32(v.x * inv);
    v.y = to_tf32(v.y * inv);
    v.z = to_tf32(v.z * inv);
    v.w = to_tf32(v.w * inv);
    dst[lane] = v;
}

// ---------------------------------------------------------------------------
// Kernel 2: fused attention. grid = (Sq/128, B). 256 threads (8 warps, 4x2).
// Pass 1: S = Qn Kn^T, p = mask?exp(S):0, accumulate row sums (regs, determ.)
// Pass 2: recompute S, write attn = p/rowsum, accumulate O += p @ V, scale.
// ---------------------------------------------------------------------------
#define LDQ 132
#define LDK 132
#define LDV 136
#define SMEM_FLOATS (128*LDQ + 128*LDK + 128*LDV + 256)

__global__ __launch_bounds__(256, 1)
void attn_kernel(const float* __restrict__ v_in, const int* __restrict__ mask,
                 float* __restrict__ out, float* __restrict__ attn) {
    extern __shared__ float sm[];
    float* Qs  = sm;                    // 128 x (132)
    float* Ks  = Qs + 128 * LDQ;        // 128 x (132)   (re-used for P in pass 2)
    float* Vs  = Ks + 128 * LDK;        // 128 x (136)
    float* rws = Vs + 128 * LDV;        // 128 rows x 2 (per warp_n partial sums)

    const int tid  = threadIdx.x;
    const int lane = tid & 31;
    const int wid  = tid >> 5;
    const int wm   = wid & 3;          // warp row  (32 q-rows each)
    const int wn   = wid >> 2;         // warp col  (64 cols each)
    const int g    = lane >> 2;        // 0..7
    const int tg   = lane & 3;         // 0..3
    const int b    = blockIdx.y;
    const int q0   = blockIdx.x * 128;

    // ---- load persistent Q tile ----
    {
        const float4* src = (const float4*)(g_qn + ((size_t)b * SS + q0) * DD);
        #pragma unroll 4
        for (int i = tid; i < 128 * 32; i += 256) {
            int r = i >> 5, c = i & 31;
            *(float4*)(Qs + r * LDQ + c * 4) = src[r * 32 + c];
        }
    }

    float rs[2][2] = {{0.f, 0.f}, {0.f, 0.f}};

    // ================= PASS 1: row sums =================
    for (int t = 0; t < 32; ++t) {
        const int k0 = t * 128;
        __syncthreads();   // previous tile's mma reads of Ks done
        {
            const float4* ksrc = (const float4*)(g_kn + ((size_t)b * SS + k0) * DD);
            #pragma unroll 4
            for (int i = tid; i < 128 * 32; i += 256) {
                int r = i >> 5, c = i & 31;
                *(float4*)(Ks + r * LDK + c * 4) = ksrc[r * 32 + c];
            }
        }
        __syncthreads();

        float acc[2][8][4];
        #pragma unroll
        for (int mt = 0; mt < 2; ++mt)
            #pragma unroll
            for (int nt = 0; nt < 8; ++nt)
                #pragma unroll
                for (int i = 0; i < 4; ++i) acc[mt][nt][i] = 0.f;

        #pragma unroll
        for (int ks = 0; ks < 16; ++ks) {
            uint32_t a[2][4];
            #pragma unroll
            for (int mt = 0; mt < 2; ++mt) {
                const float* A = Qs + (wm * 32 + mt * 16 + g) * LDQ + ks * 8 + tg;
                a[mt][0] = __float_as_uint(A[0]);
                a[mt][1] = __float_as_uint(A[8 * LDQ]);
                a[mt][2] = __float_as_uint(A[4]);
                a[mt][3] = __float_as_uint(A[8 * LDQ + 4]);
            }
            #pragma unroll
            for (int nt = 0; nt < 8; ++nt) {
                const float* Bp = Ks + (wn * 64 + nt * 8 + g) * LDK + ks * 8 + tg;
                uint32_t bf[2] = { __float_as_uint(Bp[0]), __float_as_uint(Bp[4]) };
                mma8(acc[0][nt], a[0], bf);
                mma8(acc[1][nt], a[1], bf);
            }
        }

        // epilogue: mask + exp + accumulate row partials (registers)
        #pragma unroll
        for (int mt = 0; mt < 2; ++mt) {
            #pragma unroll
            for (int h = 0; h < 2; ++h) {
                const int r = wm * 32 + mt * 16 + h * 8 + g;
                const int* mrow = mask + ((size_t)b * SS + q0 + r) * SS + k0 + wn * 64;
                float part = 0.f;
                #pragma unroll
                for (int nt = 0; nt < 8; ++nt) {
                    int col = nt * 8 + tg * 2;
                    int2 mk = *(const int2*)(mrow + col);
                    float p0 = mk.x ? __expf(acc[mt][nt][h * 2 + 0]) : 0.f;
                    float p1 = mk.y ? __expf(acc[mt][nt][h * 2 + 1]) : 0.f;
                    part += p0 + p1;
                }
                rs[mt][h] += part;
            }
        }
    }

    // deterministic row-sum reduction: across tg lanes, then across warp_n via smem
    #pragma unroll
    for (int mt = 0; mt < 2; ++mt)
        #pragma unroll
        for (int h = 0; h < 2; ++h) {
            rs[mt][h] += __shfl_xor_sync(0xffffffffu, rs[mt][h], 1);
            rs[mt][h] += __shfl_xor_sync(0xffffffffu, rs[mt][h], 2);
        }
    __syncthreads();
    if (tg == 0) {
        #pragma unroll
        for (int mt = 0; mt < 2; ++mt)
            #pragma unroll
            for (int h = 0; h < 2; ++h) {
                int r = wm * 32 + mt * 16 + h * 8 + g;
                rws[r * 2 + wn] = rs[mt][h];
            }
    }
    __syncthreads();
    float inv[2][2];
    #pragma unroll
    for (int mt = 0; mt < 2; ++mt)
        #pragma unroll
        for (int h = 0; h < 2; ++h) {
            int r = wm * 32 + mt * 16 + h * 8 + g;
            inv[mt][h] = 1.0f / (rws[r * 2 + 0] + rws[r * 2 + 1]);
        }

    float accO[2][8][4];
    #pragma unroll
    for (int mt = 0; mt < 2; ++mt)
        #pragma unroll
        for (int nt = 0; nt < 8; ++nt)
            #pragma unroll
            for (int i = 0; i < 4; ++i) accO[mt][nt][i] = 0.f;

    // ================= PASS 2: attn write + O accumulation =================
    for (int t = 0; t < 32; ++t) {
        const int k0 = t * 128;
        __syncthreads();   // previous PV mma reads of Ks(P)/Vs done
        {
            const float4* ksrc = (const float4*)(g_kn + ((size_t)b * SS + k0) * DD);
            const float4* vsrc = (const float4*)(v_in + ((size_t)b * SS + k0) * DD);
            #pragma unroll 2
            for (int i = tid; i < 128 * 32; i += 256) {
                int r = i >> 5, c = i & 31;
                *(float4*)(Ks + r * LDK + c * 4) = ksrc[r * 32 + c];
                float4 vv = vsrc[r * 32 + c];
                vv.x = to_tf32(vv.x); vv.y = to_tf32(vv.y);
                vv.z = to_tf32(vv.z); vv.w = to_tf32(vv.w);
                *(float4*)(Vs + r * LDV + c * 4) = vv;
            }
        }
        __syncthreads();

        float acc[2][8][4];
        #pragma unroll
        for (int mt = 0; mt < 2; ++mt)
            #pragma unroll
            for (int nt = 0; nt < 8; ++nt)
                #pragma unroll
                for (int i = 0; i < 4; ++i) acc[mt][nt][i] = 0.f;

        #pragma unroll
        for (int ks = 0; ks < 16; ++ks) {
            uint32_t a[2][4];
            #pragma unroll
            for (int mt = 0; mt < 2; ++mt) {
                const float* A = Qs + (wm * 32 + mt * 16 + g) * LDQ + ks * 8 + tg;
                a[mt][0] = __float_as_uint(A[0]);
                a[mt][1] = __float_as_uint(A[8 * LDQ]);
                a[mt][2] = __float_as_uint(A[4]);
                a[mt][3] = __float_as_uint(A[8 * LDQ + 4]);
            }
            #pragma unroll
            for (int nt = 0; nt < 8; ++nt) {
                const float* Bp = Ks + (wn * 64 + nt * 8 + g) * LDK + ks * 8 + tg;
                uint32_t bf[2] = { __float_as_uint(Bp[0]), __float_as_uint(Bp[4]) };
                mma8(acc[0][nt], a[0], bf);
                mma8(acc[1][nt], a[1], bf);
            }
        }
        __syncthreads();   // all Ks reads finished; safe to overwrite with P

        // epilogue: p, write normalized attn, stash tf32(p) into Ks (as P)
        #pragma unroll
        for (int mt = 0; mt < 2; ++mt) {
            #pragma unroll
            for (int h = 0; h < 2; ++h) {
                const int r = wm * 32 + mt * 16 + h * 8 + g;
                const float iv = inv[mt][h];
                const int* mrow = mask + ((size_t)b * SS + q0 + r) * SS + k0 + wn * 64;
                float* arow = attn + ((size_t)b * SS + q0 + r) * SS + k0 + wn * 64;
                #pragma unroll
                for (int nt = 0; nt < 8; ++nt) {
                    int col = nt * 8 + tg * 2;
                    int2 mk = *(const int2*)(mrow + col);
                    float p0 = mk.x ? __expf(acc[mt][nt][h * 2 + 0]) : 0.f;
                    float p1 = mk.y ? __expf(acc[mt][nt][h * 2 + 1]) : 0.f;
                    *(float2*)(arow + col) = make_float2(p0 * iv, p1 * iv);
                    *(float2*)(Ks + r * LDK + wn * 64 + col) =
                        make_float2(to_tf32(p0), to_tf32(p1));
                }
            }
        }
        __syncthreads();

        // PV: accO += P @ V
        #pragma unroll
        for (int ks = 0; ks < 16; ++ks) {
            uint32_t a[2][4];
            #pragma unroll
            for (int mt = 0; mt < 2; ++mt) {
                const float* A = Ks + (wm * 32 + mt * 16 + g) * LDK + ks * 8 + tg;
                a[mt][0] = __float_as_uint(A[0]);
                a[mt][1] = __float_as_uint(A[8 * LDK]);
                a[mt][2] = __float_as_uint(A[4]);
                a[mt][3] = __float_as_uint(A[8 * LDK + 4]);
            }
            #pragma unroll
            for (int nt = 0; nt < 8; ++nt) {
                const float* Bp = Vs + (ks * 8 + tg) * LDV + wn * 64 + nt * 8 + g;
                uint32_t bf[2] = { __float_as_uint(Bp[0]), __float_as_uint(Bp[4 * LDV]) };
                mma8(accO[0][nt], a[0], bf);
                mma8(accO[1][nt], a[1], bf);
            }
        }
    }

    // ---- write O (scaled by inverse row sums) ----
    #pragma unroll
    for (int mt = 0; mt < 2; ++mt) {
        #pragma unroll
        for (int h = 0; h < 2; ++h) {
            const int r = wm * 32 + mt * 16 + h * 8 + g;
            const float iv = inv[mt][h];
            float* orow = out + ((size_t)b * SS + q0 + r) * DD + wn * 64;
            #pragma unroll
            for (int nt = 0; nt < 8; ++nt) {
                int col = nt * 8 + tg * 2;
                *(float2*)(orow + col) = make_float2(accO[mt][nt][h * 2 + 0] * iv,
                                                     accO[mt][nt][h * 2 + 1] * iv);
            }
        }
    }
}

// ---------------------------------------------------------------------------
extern "C" void kernel_launch(void* const* d_in, const int* in_sizes, int n_in,
                              void* d_out, int out_size) {
    const float* q    = (const float*)d_in[0];
    const float* k    = (const float*)d_in[1];
    const float* v    = (const float*)d_in[2];
    const int*   mask = (const int*)d_in[3];
    const float* temp = (const float*)d_in[4];

    float* out  = (float*)d_out;                       // [B,Sq,D]
    float* attn = out + (size_t)BB * SS * DD;          // [B,Sq,Sk]

    // normalize (32768 rows, one warp each)
    norm_kernel<<<(2 * BB * SS) / 8, 256>>>(q, k, temp);

    // fused attention
    size_t smem = SMEM_FLOATS * sizeof(float);
    cudaFuncSetAttribute(attn_kernel, cudaFuncAttributeMaxDynamicSharedMemorySize,
                         (int)smem);
    dim3 grid(SS / 128, BB);
    attn_kernel<<<grid, 256, smem>>>(v, mask, out, attn);
}

// round 2
// speedup vs baseline: 1.6051x; 1.6051x over previous
#include <cuda_runtime.h>
#include <cuda_bf16.h>
#include <cstdint>

#define BB 4
#define SS 4096
#define DD 128

// scratch: normalized q (scaled by 1/temp, tf32), normalized k, packed mask bits
__device__ float g_qn[(size_t)BB * SS * DD];
__device__ float g_kn[(size_t)BB * SS * DD];
__device__ uint32_t g_bits[(size_t)BB * SS * SS / 32];

__device__ __forceinline__ float to_tf32(float x) {
    asm("cvt.rna.tf32.f32 %0, %0;" : "+f"(x));
    return x;
}

__device__ __forceinline__ void mma8(float c[4], const uint32_t a[4], const uint32_t b[2]) {
    asm volatile(
        "mma.sync.aligned.m16n8k8.row.col.f32.tf32.tf32.f32 "
        "{%0,%1,%2,%3}, {%4,%5,%6,%7}, {%8,%9}, {%0,%1,%2,%3};"
        : "+f"(c[0]), "+f"(c[1]), "+f"(c[2]), "+f"(c[3])
        : "r"(a[0]), "r"(a[1]), "r"(a[2]), "r"(a[3]), "r"(b[0]), "r"(b[1]));
}

__device__ __forceinline__ void cpa16(float* dst, const float* src) {
    unsigned sa = (unsigned)__cvta_generic_to_shared(dst);
    asm volatile("cp.async.cg.shared.global [%0], [%1], 16;" :: "r"(sa), "l"(src));
}
#define CP_COMMIT() asm volatile("cp.async.commit_group;")
#define CP_WAIT(N)  asm volatile("cp.async.wait_group %0;" :: "n"(N))

// ---------------------------------------------------------------------------
// Kernel 0: pack mask int32 -> 1 bit per element. One warp packs 1024 elems.
// ---------------------------------------------------------------------------
__global__ __launch_bounds__(256)
void pack_mask_kernel(const int* __restrict__ mask) {
    size_t warp = (size_t)blockIdx.x * 8 + (threadIdx.x >> 5);
    int lane = threadIdx.x & 31;
    size_t base = warp * 1024;
    uint32_t myw = 0;
    #pragma unroll
    for (int j = 0; j < 32; ++j) {
        int v = mask[base + (size_t)j * 32 + lane];
        uint32_t bal = __ballot_sync(0xffffffffu, v != 0);
        if (lane == j) myw = bal;
    }
    g_bits[base / 32 + lane] = myw;
}

// ---------------------------------------------------------------------------
// Kernel 1: L2-normalize q (scaled by 1/temp) and k; tf32-round both.
// ---------------------------------------------------------------------------
__global__ __launch_bounds__(256)
void norm_kernel(const float* __restrict__ q, const float* __restrict__ k,
                 const float* __restrict__ temp) {
    int warp = (blockIdx.x * blockDim.x + threadIdx.x) >> 5;
    int lane = threadIdx.x & 31;
    if (warp >= 2 * BB * SS) return;
    bool is_q = warp < BB * SS;
    size_t row = is_q ? (size_t)warp : (size_t)(warp - BB * SS);
    const float4* src = (const float4*)((is_q ? q : k) + row * DD);
    float4* dst = (float4*)((is_q ? g_qn : g_kn) + row * DD);

    float4 v = src[lane];
    float ss = v.x * v.x + v.y * v.y + v.z * v.z + v.w * v.w;
    #pragma unroll
    for (int o = 16; o > 0; o >>= 1) ss += __shfl_xor_sync(0xffffffffu, ss, o);
    float n = sqrtf(ss);
    float inv = 1.0f / fmaxf(n, 1e-12f);
    if (is_q) inv *= (1.0f / temp[0]);
    v.x = to_tf32(v.x * inv);
    v.y = to_tf32(v.y * inv);
    v.z = to_tf32(v.z * inv);
    v.w = to_tf32(v.w * inv);
    dst[lane] = v;
}

// ---------------------------------------------------------------------------
// Kernel 2: fused attention, 512 threads (16 warps, 4x4), cp.async pipelined.
// Pass 1: rowsums over 128-col K tiles (double-buffered).
// Pass 2: 64-row K/V subtiles; recompute S, write attn, accumulate O.
// ---------------------------------------------------------------------------
#define LDQ 132
#define LDK 132
#define LDV 136
#define LDP 68

#define Q_OFF   0
#define K1_OFF  16896              /* pass1: 2 x 128 x 132               */
#define K2_OFF  16896              /* pass2: 2 x 64 x 132 = 16896        */
#define V_OFF   (K2_OFF + 16896)   /* 64 x 136 = 8704                    */
#define P_OFF   (V_OFF + 8704)     /* 128 x 68 = 8704                    */
#define RWS_OFF 51200
#define SMEM_FLOATS (RWS_OFF + 512)

__global__ __launch_bounds__(512, 1)
void attn_kernel(const float* __restrict__ v_in,
                 float* __restrict__ out, float* __restrict__ attn) {
    extern __shared__ float sm[];
    float* Qs = sm + Q_OFF;

    const int tid  = threadIdx.x;
    const int lane = tid & 31;
    const int wid  = tid >> 5;
    const int wm   = wid & 3;            // 4 m-warps x 32 q-rows
    const int wn   = wid >> 2;           // 4 n-warps
    const int g    = lane >> 2;          // 0..7
    const int tg   = lane & 3;           // 0..3
    const int b    = blockIdx.y;
    const int q0   = blockIdx.x * 128;

    const float* kbase = g_kn + ((size_t)b * SS) * DD;
    const float* vbase = v_in + ((size_t)b * SS) * DD;
    const uint32_t* bitbase = g_bits + ((size_t)b * SS + q0) * (SS / 32);

    // prologue: Q tile + K tile 0 via cp.async (one group)
    {
        const float* qsrc = g_qn + ((size_t)b * SS + q0) * DD;
        #pragma unroll
        for (int i = tid; i < 128 * 32; i += 512) {
            int r = i >> 5, c = i & 31;
            cpa16(Qs + r * LDQ + c * 4, qsrc + r * DD + c * 4);
        }
        float* Kb = sm + K1_OFF;
        #pragma unroll
        for (int i = tid; i < 128 * 32; i += 512) {
            int r = i >> 5, c = i & 31;
            cpa16(Kb + r * LDK + c * 4, kbase + r * DD + c * 4);
        }
        CP_COMMIT();
    }

    float rs[2][2] = {{0.f, 0.f}, {0.f, 0.f}};

    // ================= PASS 1: row sums (32 tiles of 128) =================
    for (int t = 0; t < 32; ++t) {
        const int k0 = t * 128;
        // prefetch next tile
        if (t + 1 < 32) {
            float* Kb = sm + K1_OFF + ((t + 1) & 1) * (128 * LDK);
            #pragma unroll
            for (int i = tid; i < 128 * 32; i += 512) {
                int r = i >> 5, c = i & 31;
                cpa16(Kb + r * LDK + c * 4, kbase + (size_t)(k0 + 128 + r) * DD + c * 4);
            }
        }
        CP_COMMIT();
        CP_WAIT(1);
        __syncthreads();

        const float* Ks = sm + K1_OFF + (t & 1) * (128 * LDK);

        float acc[2][4][4];
        #pragma unroll
        for (int mt = 0; mt < 2; ++mt)
            #pragma unroll
            for (int nt = 0; nt < 4; ++nt)
                #pragma unroll
                for (int i = 0; i < 4; ++i) acc[mt][nt][i] = 0.f;

        #pragma unroll
        for (int ks = 0; ks < 16; ++ks) {
            uint32_t a[2][4];
            #pragma unroll
            for (int mt = 0; mt < 2; ++mt) {
                const float* A = Qs + (wm * 32 + mt * 16 + g) * LDQ + ks * 8 + tg;
                a[mt][0] = __float_as_uint(A[0]);
                a[mt][1] = __float_as_uint(A[8 * LDQ]);
                a[mt][2] = __float_as_uint(A[4]);
                a[mt][3] = __float_as_uint(A[8 * LDQ + 4]);
            }
            #pragma unroll
            for (int nt = 0; nt < 4; ++nt) {
                const float* Bp = Ks + (wn * 32 + nt * 8 + g) * LDK + ks * 8 + tg;
                uint32_t bf[2] = { __float_as_uint(Bp[0]), __float_as_uint(Bp[4]) };
                mma8(acc[0][nt], a[0], bf);
                mma8(acc[1][nt], a[1], bf);
            }
        }

        // epilogue: bitmask + exp + row-partials (registers only)
        #pragma unroll
        for (int mt = 0; mt < 2; ++mt) {
            #pragma unroll
            for (int h = 0; h < 2; ++h) {
                const int r = wm * 32 + mt * 16 + h * 8 + g;
                uint32_t w = bitbase[(size_t)r * 128 + (k0 >> 5) + wn];
                float part = 0.f;
                #pragma unroll
                for (int nt = 0; nt < 4; ++nt) {
                    int j = nt * 8 + tg * 2;
                    float m0 = (float)((w >> j) & 1u);
                    float m1 = (float)((w >> (j + 1)) & 1u);
                    part += m0 * __expf(acc[mt][nt][h * 2 + 0])
                          + m1 * __expf(acc[mt][nt][h * 2 + 1]);
                }
                rs[mt][h] += part;
            }
        }
        __syncthreads();   // all reads of Ks buffer done before it is refilled
    }

    // deterministic row-sum reduction: tg lanes -> smem across wn warps
    #pragma unroll
    for (int mt = 0; mt < 2; ++mt)
        #pragma unroll
        for (int h = 0; h < 2; ++h) {
            rs[mt][h] += __shfl_xor_sync(0xffffffffu, rs[mt][h], 1);
            rs[mt][h] += __shfl_xor_sync(0xffffffffu, rs[mt][h], 2);
        }
    float* rws = sm + RWS_OFF;
    if (tg == 0) {
        #pragma unroll
        for (int mt = 0; mt < 2; ++mt)
            #pragma unroll
            for (int h = 0; h < 2; ++h) {
                int r = wm * 32 + mt * 16 + h * 8 + g;
                rws[r * 4 + wn] = rs[mt][h];
            }
    }
    __syncthreads();
    float inv[2][2];
    #pragma unroll
    for (int mt = 0; mt < 2; ++mt)
        #pragma unroll
        for (int h = 0; h < 2; ++h) {
            int r = wm * 32 + mt * 16 + h * 8 + g;
            inv[mt][h] = 1.0f / (rws[r * 4 + 0] + rws[r * 4 + 1] +
                                 rws[r * 4 + 2] + rws[r * 4 + 3]);
        }
    __syncthreads();   // rws read done; smem region reused below

    float accO[2][4][4];
    #pragma unroll
    for (int mt = 0; mt < 2; ++mt)
        #pragma unroll
        for (int nt = 0; nt < 4; ++nt)
            #pragma unroll
            for (int i = 0; i < 4; ++i) accO[mt][nt][i] = 0.f;

    // prologue pass2: K[0] (group), V[0] (group)
    {
        float* Kb = sm + K2_OFF;
        #pragma unroll
        for (int i = tid; i < 64 * 32; i += 512) {
            int r = i >> 5, c = i & 31;
            cpa16(Kb + r * LDK + c * 4, kbase + r * DD + c * 4);
        }
        CP_COMMIT();
        float* Vb = sm + V_OFF;
        #pragma unroll
        for (int i = tid; i < 64 * 32; i += 512) {
            int r = i >> 5, c = i & 31;
            cpa16(Vb + r * LDV + c * 4, vbase + r * DD + c * 4);
        }
        CP_COMMIT();
    }

    // ================= PASS 2: 64 tiles of 64 K/V rows =================
    for (int t = 0; t < 64; ++t) {
        const int k0 = t * 64;
        // prefetch K[t+1]
        if (t + 1 < 64) {
            float* Kb = sm + K2_OFF + ((t + 1) & 1) * (64 * LDK);
            #pragma unroll
            for (int i = tid; i < 64 * 32; i += 512) {
                int r = i >> 5, c = i & 31;
                cpa16(Kb + r * LDK + c * 4, kbase + (size_t)(k0 + 64 + r) * DD + c * 4);
            }
        }
        CP_COMMIT();
        CP_WAIT(2);          // K[t] complete (V[t], K[t+1] may pend)
        __syncthreads();

        const float* Ks = sm + K2_OFF + (t & 1) * (64 * LDK);
        float* Ps = sm + P_OFF;
        const float* Vs = sm + V_OFF;

        // S = Q K^T  (m=128, n=64, k=128)
        float acc[2][2][4];
        #pragma unroll
        for (int mt = 0; mt < 2; ++mt)
            #pragma unroll
            for (int nt = 0; nt < 2; ++nt)
                #pragma unroll
                for (int i = 0; i < 4; ++i) acc[mt][nt][i] = 0.f;

        #pragma unroll
        for (int ks = 0; ks < 16; ++ks) {
            uint32_t a[2][4];
            #pragma unroll
            for (int mt = 0; mt < 2; ++mt) {
                const float* A = Qs + (wm * 32 + mt * 16 + g) * LDQ + ks * 8 + tg;
                a[mt][0] = __float_as_uint(A[0]);
                a[mt][1] = __float_as_uint(A[8 * LDQ]);
                a[mt][2] = __float_as_uint(A[4]);
                a[mt][3] = __float_as_uint(A[8 * LDQ + 4]);
            }
            #pragma unroll
            for (int nt = 0; nt < 2; ++nt) {
                const float* Bp = Ks + (wn * 16 + nt * 8 + g) * LDK + ks * 8 + tg;
                uint32_t bf[2] = { __float_as_uint(Bp[0]), __float_as_uint(Bp[4]) };
                mma8(acc[0][nt], a[0], bf);
                mma8(acc[1][nt], a[1], bf);
            }
        }

        // epilogue: p, write attn, stash P (tf32) in smem
        #pragma unroll
        for (int mt = 0; mt < 2; ++mt) {
            #pragma unroll
            for (int h = 0; h < 2; ++h) {
                const int r = wm * 32 + mt * 16 + h * 8 + g;
                const float iv = inv[mt][h];
                uint32_t w = bitbase[(size_t)r * 128 + (k0 >> 5) + (wn >> 1)];
                int jb = (wn & 1) * 16;
                float* arow = attn + ((size_t)b * SS + q0 + r) * SS + k0 + wn * 16;
                #pragma unroll
                for (int nt = 0; nt < 2; ++nt) {
                    int j = jb + nt * 8 + tg * 2;
                    float m0 = (float)((w >> j) & 1u);
                    float m1 = (float)((w >> (j + 1)) & 1u);
                    float p0 = m0 * __expf(acc[mt][nt][h * 2 + 0]);
                    float p1 = m1 * __expf(acc[mt][nt][h * 2 + 1]);
                    int col = nt * 8 + tg * 2;
                    *(float2*)(arow + col) = make_float2(p0 * iv, p1 * iv);
                    *(float2*)(Ps + r * LDP + wn * 16 + col) =
                        make_float2(to_tf32(p0), to_tf32(p1));
                }
            }
        }

        CP_WAIT(1);          // V[t] complete (K[t+1] may pend)
        __syncthreads();     // P + V visible to all

        // O += P V  (m=128, n=128, k=64)
        #pragma unroll
        for (int ks = 0; ks < 8; ++ks) {
            uint32_t a[2][4];
            #pragma unroll
            for (int mt = 0; mt < 2; ++mt) {
                const float* A = Ps + (wm * 32 + mt * 16 + g) * LDP + ks * 8 + tg;
                a[mt][0] = __float_as_uint(A[0]);
                a[mt][1] = __float_as_uint(A[8 * LDP]);
                a[mt][2] = __float_as_uint(A[4]);
                a[mt][3] = __float_as_uint(A[8 * LDP + 4]);
            }
            #pragma unroll
            for (int nt = 0; nt < 4; ++nt) {
                const float* Bp = Vs + (ks * 8 + tg) * LDV + wn * 32 + nt * 8 + g;
                uint32_t bf[2] = { __float_as_uint(Bp[0]), __float_as_uint(Bp[4 * LDV]) };
                mma8(accO[0][nt], a[0], bf);
                mma8(accO[1][nt], a[1], bf);
            }
        }
        __syncthreads();     // PV reads done: V buffer & P free for next iter

        // issue V[t+1]
        if (t + 1 < 64) {
            float* Vb = sm + V_OFF;
            #pragma unroll
            for (int i = tid; i < 64 * 32; i += 512) {
                int r = i >> 5, c = i & 31;
                cpa16(Vb + r * LDV + c * 4, vbase + (size_t)(k0 + 64 + r) * DD + c * 4);
            }
        }
        CP_COMMIT();
    }

    // ---- write O (scaled by inverse row sums) ----
    #pragma unroll
    for (int mt = 0; mt < 2; ++mt) {
        #pragma unroll
        for (int h = 0; h < 2; ++h) {
            const int r = wm * 32 + mt * 16 + h * 8 + g;
            const float iv = inv[mt][h];
            float* orow = out + ((size_t)b * SS + q0 + r) * DD + wn * 32;
            #pragma unroll
            for (int nt = 0; nt < 4; ++nt) {
                int col = nt * 8 + tg * 2;
                *(float2*)(orow + col) = make_float2(accO[mt][nt][h * 2 + 0] * iv,
                                                     accO[mt][nt][h * 2 + 1] * iv);
            }
        }
    }
}

// ---------------------------------------------------------------------------
extern "C" void kernel_launch(void* const* d_in, const int* in_sizes, int n_in,
                              void* d_out, int out_size) {
    const float* q    = (const float*)d_in[0];
    const float* k    = (const float*)d_in[1];
    const float* v    = (const float*)d_in[2];
    const int*   mask = (const int*)d_in[3];
    const float* temp = (const float*)d_in[4];

    float* out  = (float*)d_out;                   // [B,Sq,D]
    float* attn = out + (size_t)BB * SS * DD;      // [B,Sq,Sk]

    // pack mask to bits: 2^26 elems / 1024 per warp / 8 warps per block
    pack_mask_kernel<<<(BB * SS * SS) / 1024 / 8, 256>>>(mask);

    // normalize (32768 rows, one warp each)
    norm_kernel<<<(2 * BB * SS) / 8, 256>>>(q, k, temp);

    // fused attention
    size_t smem = SMEM_FLOATS * sizeof(float);
    cudaFuncSetAttribute(attn_kernel, cudaFuncAttributeMaxDynamicSharedMemorySize,
                         (int)smem);
    dim3 grid(SS / 128, BB);
    attn_kernel<<<grid, 512, smem>>>(v, out, attn);
}